// round 4
// baseline (speedup 1.0000x reference)
#include <cuda_runtime.h>
#include <cstddef>

// Problem constants (fixed by the dataset)
#define BS    32
#define NFEAT 64
#define NN    512      // N (graph nodes / m dim)
#define JJ    4
#define NOUT  128
#define CDIM  (JJ * NFEAT)        // 256 channels
#define ROWF4 512                 // one W n-row = 2048 floats = 512 float4
#define NCHUNK 32                 // n-chunks per batch in kernel 1
#define NPERCHUNK (NN / NCHUNK)   // 16

// Scratch 1: per-(b,chunk) partial sums of W over n. 32*32*2048 floats = 8 MB.
// Written with default caching -> stays L2-resident for kernel 2.
__device__ float g_Spart[BS * NCHUNK * 2048];
// Scratch 2: fully reduced, transposed S[b][j][m]. 32*4*512 floats = 256 KB.
__device__ float g_S[BS * JJ * NN];
// G[b][c], c = j*64+f. 32 KB.
__device__ float g_G[BS * CDIM];

// ---------------------------------------------------------------------------
// Kernel 1 (the 134 MB HBM stream): Spart[b,chunk,slot] = sum of 16 n-rows.
// Row-based: 512 threads x float4 = one whole 8KB n-row per iteration, fully
// coalesced; full unroll gives MLP=16 per thread. Proven 74.5% DRAM shape.
// ---------------------------------------------------------------------------
__global__ __launch_bounds__(512) void reduce_w_kernel(const float4* __restrict__ W4) {
    const int b     = blockIdx.x;
    const int chunk = blockIdx.y;
    const int t     = threadIdx.x;          // 0..511

    const size_t row0 = ((size_t)b * NN + (size_t)chunk * NPERCHUNK) * ROWF4;
    const float4* __restrict__ base = W4 + row0;

    float4 acc = make_float4(0.f, 0.f, 0.f, 0.f);
#pragma unroll
    for (int i = 0; i < NPERCHUNK; ++i) {
        // streaming, evict-first: W is read exactly once and exceeds L2
        float4 v = __ldcs(&base[(size_t)i * ROWF4 + t]);
        acc.x += v.x; acc.y += v.y; acc.z += v.z; acc.w += v.w;
    }

    // default caching: keep partials hot in L2 for kernel 2
    float4* out4 = reinterpret_cast<float4*>(g_Spart);
    out4[((size_t)b * NCHUNK + chunk) * ROWF4 + t] = acc;
}

// ---------------------------------------------------------------------------
// Kernel 2: S[b][j][m] = sum over 32 chunks of Spart[b][c][m*4+j].
// grid (32, 8) x 256 thr, one thread per slot. Reads are coalesced (fixed
// chunk -> contiguous slots) and L2-hot. Transposed write is only 256 KB.
// ---------------------------------------------------------------------------
__global__ __launch_bounds__(256) void reduce_chunks_kernel() {
    const int b    = blockIdx.x;
    const int slot = blockIdx.y * 256 + threadIdx.x;   // 0..2047, slot = m*4+j

    const float* __restrict__ part = g_Spart + (size_t)b * NCHUNK * 2048 + slot;
    float a = 0.f;
#pragma unroll
    for (int c = 0; c < NCHUNK; ++c) a += part[(size_t)c * 2048];

    const int m = slot >> 2;
    const int j = slot & 3;
    g_S[((size_t)b * JJ + j) * NN + m] = a;
}

// ---------------------------------------------------------------------------
// Kernel 3: G[b][j*64+f] = sum_m S[b][j][m] * X[b][f][m]
// grid (32, 32) x 256 thr; one warp per output c. Both streams coalesced
// (m = lane + 32*i), shfl tree-reduce. S is L2-hot; X is 4 MB.
// ---------------------------------------------------------------------------
__global__ __launch_bounds__(256) void compute_g_kernel(const float* __restrict__ X) {
    const int b    = blockIdx.x;
    const int c    = blockIdx.y * 8 + (threadIdx.x >> 5);  // 0..255
    const int lane = threadIdx.x & 31;
    const int j    = c >> 6;
    const int f    = c & 63;

    const float* __restrict__ Sr = g_S + ((size_t)b * JJ + j) * NN;
    const float* __restrict__ Xr = X   + ((size_t)b * NFEAT + f) * NN;

    float a = 0.f;
#pragma unroll
    for (int i = 0; i < 16; ++i) {
        const int m = i * 32 + lane;
        a += Sr[m] * Xr[m];
    }
#pragma unroll
    for (int s = 16; s > 0; s >>= 1) a += __shfl_xor_sync(0xffffffffu, a, s);

    if (lane == 0) g_G[(size_t)b * CDIM + c] = a;
}

// ---------------------------------------------------------------------------
// Kernel 4: y[b][o] = sum_c fc_w[o][c] * G[b][c] + 512 * fc_b[o]
// grid 32 x 128 thr; float4 loads, everything L2-hot, trivial.
// ---------------------------------------------------------------------------
__global__ __launch_bounds__(128) void compute_y_kernel(
    const float* __restrict__ fc_w,
    const float* __restrict__ fc_b,
    float* __restrict__ out)
{
    const int b = blockIdx.x;
    const int o = threadIdx.x;   // 0..127

    const float4* __restrict__ w4 = reinterpret_cast<const float4*>(fc_w + (size_t)o * CDIM);
    const float4* __restrict__ g4 = reinterpret_cast<const float4*>(g_G + (size_t)b * CDIM);

    float y = (float)NN * fc_b[o];
#pragma unroll
    for (int q = 0; q < CDIM / 4; ++q) {
        const float4 w = w4[q];
        const float4 g = g4[q];
        y += w.x * g.x + w.y * g.y + w.z * g.z + w.w * g.w;
    }
    out[(size_t)b * NOUT + o] = y;
}

// ---------------------------------------------------------------------------
// Inputs (metadata order): X[32,64,512] f32, W[32,512,512,4] f32,
// fc_w[128,256] f32, fc_b[128] f32, N_batch (int), mask[32,512] f32 (unused).
// Output: y[32,128] f32.
// ---------------------------------------------------------------------------
extern "C" void kernel_launch(void* const* d_in, const int* in_sizes, int n_in,
                              void* d_out, int out_size)
{
    const float* X    = (const float*)d_in[0];
    const float* W    = (const float*)d_in[1];
    const float* fc_w = (const float*)d_in[2];
    const float* fc_b = (const float*)d_in[3];
    float*       out  = (float*)d_out;

    dim3 grid1(BS, NCHUNK);
    reduce_w_kernel<<<grid1, 512>>>(reinterpret_cast<const float4*>(W));
    dim3 grid2(BS, 8);
    reduce_chunks_kernel<<<grid2, 256>>>();
    dim3 grid3(BS, 32);
    compute_g_kernel<<<grid3, 256>>>(X);
    compute_y_kernel<<<BS, 128>>>(fc_w, fc_b, out);
}

// round 5
// speedup vs baseline: 1.2020x; 1.2020x over previous
#include <cuda_runtime.h>
#include <cstddef>

// Problem constants (fixed by the dataset)
#define BS    32
#define NFEAT 64
#define NN    512      // N (graph nodes / m dim)
#define JJ    4
#define NOUT  128
#define CDIM  (JJ * NFEAT)        // 256 channels
#define ROWF4 512                 // one W n-row = 2048 floats = 512 float4
#define NCHUNK 32                 // n-chunks per batch in kernel 1
#define NPERCHUNK (NN / NCHUNK)   // 16

// Scratch 1: per-(b,chunk) partial sums of W over n. 32*32*2048 floats = 8 MB.
// Written with default caching -> stays L2-resident for kernel 2.
__device__ float g_Spart[BS * NCHUNK * 2048];
// Scratch 2: fully reduced, transposed S[b][j][m]. 256 KB, L2-hot.
__device__ float g_S[BS * JJ * NN];
// G[b][c], c = j*64+f. 32 KB, L2-hot.
__device__ float g_G[BS * CDIM];

// ---------------------------------------------------------------------------
// Kernel 1 (the 134 MB HBM stream): Spart[b,chunk,slot] = sum of 16 n-rows.
// Row-based: 512 threads x float4 = one whole 8KB n-row per iteration, fully
// coalesced; full unroll gives MLP=16 per thread. Proven 74.5%-of-HBM shape.
// ---------------------------------------------------------------------------
__global__ __launch_bounds__(512) void reduce_w_kernel(const float4* __restrict__ W4) {
    const int b     = blockIdx.x;
    const int chunk = blockIdx.y;
    const int t     = threadIdx.x;          // 0..511

    const size_t row0 = ((size_t)b * NN + (size_t)chunk * NPERCHUNK) * ROWF4;
    const float4* __restrict__ base = W4 + row0;

    float4 acc = make_float4(0.f, 0.f, 0.f, 0.f);
#pragma unroll
    for (int i = 0; i < NPERCHUNK; ++i) {
        // streaming, evict-first: W is read exactly once and exceeds L2
        float4 v = __ldcs(&base[(size_t)i * ROWF4 + t]);
        acc.x += v.x; acc.y += v.y; acc.z += v.z; acc.w += v.w;
    }

    // default caching: keep partials hot in L2 for kernel 2
    float4* out4 = reinterpret_cast<float4*>(g_Spart);
    out4[((size_t)b * NCHUNK + chunk) * ROWF4 + t] = acc;
}

// ---------------------------------------------------------------------------
// Kernel 2: S[b][j][m] = sum over 32 chunks of Spart[b][c][m*4+j].
// grid (32, 8) x 256 thr, one thread per slot. Coalesced, L2-hot reads;
// transposed write is only 256 KB.
// ---------------------------------------------------------------------------
__global__ __launch_bounds__(256) void reduce_chunks_kernel() {
    const int b    = blockIdx.x;
    const int slot = blockIdx.y * 256 + threadIdx.x;   // 0..2047, slot = m*4+j

    const float* __restrict__ part = g_Spart + (size_t)b * NCHUNK * 2048 + slot;
    float a = 0.f;
#pragma unroll
    for (int c = 0; c < NCHUNK; ++c) a += part[(size_t)c * 2048];

    const int m = slot >> 2;
    const int j = slot & 3;
    g_S[((size_t)b * JJ + j) * NN + m] = a;
}

// ---------------------------------------------------------------------------
// Kernel 3: G[b][j*64+f] = sum_m S[b][j][m] * X[b][f][m]
// grid (32, 32) x 256 thr; one warp per output c. Coalesced, shfl reduce.
// ---------------------------------------------------------------------------
__global__ __launch_bounds__(256) void compute_g_kernel(const float* __restrict__ X) {
    const int b    = blockIdx.x;
    const int c    = blockIdx.y * 8 + (threadIdx.x >> 5);  // 0..255
    const int lane = threadIdx.x & 31;
    const int j    = c >> 6;
    const int f    = c & 63;

    const float* __restrict__ Sr = g_S + ((size_t)b * JJ + j) * NN;
    const float* __restrict__ Xr = X   + ((size_t)b * NFEAT + f) * NN;

    float a = 0.f;
#pragma unroll
    for (int i = 0; i < 16; ++i) {
        const int m = i * 32 + lane;
        a += Sr[m] * Xr[m];
    }
#pragma unroll
    for (int s = 16; s > 0; s >>= 1) a += __shfl_xor_sync(0xffffffffu, a, s);

    if (lane == 0) g_G[(size_t)b * CDIM + c] = a;
}

// ---------------------------------------------------------------------------
// Kernel 4 (rebuilt): y[b][o] = fc_w[o,:] . G[b,:] + 512*fc_b[o]
// One warp per (b,o): grid (32, 16) x 256 thr = 4096 warps. Each lane loads
// 2 lane-strided float4s of fc_w and G (coalesced), shfl tree-reduce.
// Latency per warp ~2 load waves; chip-filling parallelism.
// ---------------------------------------------------------------------------
__global__ __launch_bounds__(256) void compute_y_kernel(
    const float* __restrict__ fc_w,
    const float* __restrict__ fc_b,
    float* __restrict__ out)
{
    const int b    = blockIdx.x;
    const int o    = blockIdx.y * 8 + (threadIdx.x >> 5);  // 0..127
    const int lane = threadIdx.x & 31;

    const float4* __restrict__ w4 = reinterpret_cast<const float4*>(fc_w + (size_t)o * CDIM);
    const float4* __restrict__ g4 = reinterpret_cast<const float4*>(g_G + (size_t)b * CDIM);

    float a = 0.f;
#pragma unroll
    for (int i = 0; i < 2; ++i) {
        const int q = i * 32 + lane;       // 0..63 float4 slots, coalesced
        const float4 w = w4[q];
        const float4 g = g4[q];
        a += w.x * g.x + w.y * g.y + w.z * g.z + w.w * g.w;
    }
#pragma unroll
    for (int s = 16; s > 0; s >>= 1) a += __shfl_xor_sync(0xffffffffu, a, s);

    if (lane == 0) out[(size_t)b * NOUT + o] = a + (float)NN * fc_b[o];
}

// ---------------------------------------------------------------------------
// Inputs (metadata order): X[32,64,512] f32, W[32,512,512,4] f32,
// fc_w[128,256] f32, fc_b[128] f32, N_batch (int), mask[32,512] f32 (unused).
// Output: y[32,128] f32.
// ---------------------------------------------------------------------------
extern "C" void kernel_launch(void* const* d_in, const int* in_sizes, int n_in,
                              void* d_out, int out_size)
{
    const float* X    = (const float*)d_in[0];
    const float* W    = (const float*)d_in[1];
    const float* fc_w = (const float*)d_in[2];
    const float* fc_b = (const float*)d_in[3];
    float*       out  = (float*)d_out;

    dim3 grid1(BS, NCHUNK);
    reduce_w_kernel<<<grid1, 512>>>(reinterpret_cast<const float4*>(W));
    dim3 grid2(BS, 8);
    reduce_chunks_kernel<<<grid2, 256>>>();
    dim3 grid3(BS, 32);
    compute_g_kernel<<<grid3, 256>>>(X);
    dim3 grid4(BS, 16);
    compute_y_kernel<<<grid4, 256>>>(fc_w, fc_b, out);
}

// round 6
// speedup vs baseline: 1.2508x; 1.0406x over previous
#include <cuda_runtime.h>
#include <cstddef>

// Problem constants (fixed by the dataset)
#define BS    32
#define NFEAT 64
#define NN    512      // N (graph nodes / m dim)
#define JJ    4
#define NOUT  128
#define CDIM  (JJ * NFEAT)        // 256 channels
#define ROWF4 512                 // one W n-row = 2048 floats = 512 float4
#define NCHUNK 16                 // n-chunks per batch in kernel 1
#define NPERCHUNK (NN / NCHUNK)   // 32

// Scratch: per-(b,chunk) partial sums of W over n. 32*16*2048 floats = 4 MB.
// Written with default caching -> stays L2-resident for the epilogue.
__device__ float g_Spart[BS * NCHUNK * 2048];

// ---------------------------------------------------------------------------
// Kernel 1 (the 134 MB HBM stream): Spart[b,chunk,slot] = sum of 32 n-rows.
// Row-based: 512 threads x float4 = one whole 8KB n-row per iteration, fully
// coalesced, MLP=32 per thread. Partial write shrunk to 4 MB (NCHUNK=16).
// ---------------------------------------------------------------------------
__global__ __launch_bounds__(512) void reduce_w_kernel(const float4* __restrict__ W4) {
    const int b     = blockIdx.x;
    const int chunk = blockIdx.y;
    const int t     = threadIdx.x;          // 0..511

    const size_t row0 = ((size_t)b * NN + (size_t)chunk * NPERCHUNK) * ROWF4;
    const float4* __restrict__ base = W4 + row0;

    float4 acc = make_float4(0.f, 0.f, 0.f, 0.f);
#pragma unroll
    for (int i = 0; i < NPERCHUNK; ++i) {
        // streaming, evict-first: W is read exactly once and exceeds L2
        float4 v = __ldcs(&base[(size_t)i * ROWF4 + t]);
        acc.x += v.x; acc.y += v.y; acc.z += v.z; acc.w += v.w;
    }

    // default caching: keep partials hot in L2 for the epilogue
    float4* out4 = reinterpret_cast<float4*>(g_Spart);
    out4[((size_t)b * NCHUNK + chunk) * ROWF4 + t] = acc;
}

// ---------------------------------------------------------------------------
// Kernel 2 (fused epilogue), one block per batch b, 1024 threads:
//  phase 1: Ssh[j][m] = sum over 16 chunks of Spart[b][c][m*4+j]   (L2-hot)
//  phase 2: Gsh[j*64+f] = sum_m Ssh[j][m] * X[b][f][m]             (L2-hot)
//  phase 3: y[b][o] = fc_w[o,:] . Gsh + 512*fc_b[o]                (L2-hot)
// ---------------------------------------------------------------------------
__global__ __launch_bounds__(1024) void epilogue_kernel(
    const float* __restrict__ X,
    const float* __restrict__ fc_w,
    const float* __restrict__ fc_b,
    float* __restrict__ out)
{
    __shared__ float Ssh[JJ][NN];     // S transposed [j][m]
    __shared__ float Gsh[CDIM];       // G[j*64+f]

    const int b    = blockIdx.x;
    const int t    = threadIdx.x;     // 0..1023
    const int w    = t >> 5;          // warp 0..31
    const int lane = t & 31;

    // ---- phase 1: reduce chunk partials (coalesced: fixed c -> contiguous slots)
    const float* __restrict__ part = g_Spart + (size_t)b * NCHUNK * 2048;
#pragma unroll
    for (int i = 0; i < 2; ++i) {
        const int slot = t + i * 1024;           // 0..2047 = m*4+j
        float a = 0.f;
#pragma unroll
        for (int c = 0; c < NCHUNK; ++c) a += part[(size_t)c * 2048 + slot];
        Ssh[slot & 3][slot >> 2] = a;
    }
    __syncthreads();

    // ---- phase 2: G. Each warp handles 2 f's; lanes stride m (coalesced X).
    const float* __restrict__ Xb = X + (size_t)b * NFEAT * NN;
#pragma unroll
    for (int fi = 0; fi < 2; ++fi) {
        const int f = w * 2 + fi;                // 0..63
        float a0 = 0.f, a1 = 0.f, a2 = 0.f, a3 = 0.f;
#pragma unroll
        for (int i = 0; i < 16; ++i) {
            const int m = i * 32 + lane;
            const float xv = Xb[(size_t)f * NN + m];
            a0 += Ssh[0][m] * xv;
            a1 += Ssh[1][m] * xv;
            a2 += Ssh[2][m] * xv;
            a3 += Ssh[3][m] * xv;
        }
#pragma unroll
        for (int s = 16; s > 0; s >>= 1) {
            a0 += __shfl_xor_sync(0xffffffffu, a0, s);
            a1 += __shfl_xor_sync(0xffffffffu, a1, s);
            a2 += __shfl_xor_sync(0xffffffffu, a2, s);
            a3 += __shfl_xor_sync(0xffffffffu, a3, s);
        }
        if (lane == 0) {
            Gsh[0 * NFEAT + f] = a0;
            Gsh[1 * NFEAT + f] = a1;
            Gsh[2 * NFEAT + f] = a2;
            Gsh[3 * NFEAT + f] = a3;
        }
    }
    __syncthreads();

    // ---- phase 3: y. Each warp handles 4 o's; lanes stride c (coalesced fc_w).
#pragma unroll
    for (int oi = 0; oi < 4; ++oi) {
        const int o = w * 4 + oi;                // 0..127
        const float* __restrict__ wrow = fc_w + (size_t)o * CDIM;
        float a = 0.f;
#pragma unroll
        for (int i = 0; i < 8; ++i) {
            const int c = i * 32 + lane;
            a += wrow[c] * Gsh[c];
        }
#pragma unroll
        for (int s = 16; s > 0; s >>= 1) a += __shfl_xor_sync(0xffffffffu, a, s);
        if (lane == 0) out[(size_t)b * NOUT + o] = a + (float)NN * fc_b[o];
    }
}

// ---------------------------------------------------------------------------
// Inputs (metadata order): X[32,64,512] f32, W[32,512,512,4] f32,
// fc_w[128,256] f32, fc_b[128] f32, N_batch (int), mask[32,512] f32 (unused).
// Output: y[32,128] f32.
// ---------------------------------------------------------------------------
extern "C" void kernel_launch(void* const* d_in, const int* in_sizes, int n_in,
                              void* d_out, int out_size)
{
    const float* X    = (const float*)d_in[0];
    const float* W    = (const float*)d_in[1];
    const float* fc_w = (const float*)d_in[2];
    const float* fc_b = (const float*)d_in[3];
    float*       out  = (float*)d_out;

    dim3 grid1(BS, NCHUNK);
    reduce_w_kernel<<<grid1, 512>>>(reinterpret_cast<const float4*>(W));
    epilogue_kernel<<<BS, 1024>>>(X, fc_w, fc_b, out);
}